// round 8
// baseline (speedup 1.0000x reference)
#include <cuda_runtime.h>
#include <math.h>

// Problem dims (fixed by the dataset): x (B, K), mu (K, U), out (B, U)
#define B_DIM 8192
#define K_DIM 1024
#define N_DIM 4096

// GEMM tiling (fallback path; never taken on this dataset)
#define BM 128
#define BN 128
#define BK 16
#define TM 8
#define TN 8
#define APAD 4

#define MTILES (B_DIM / BM)   // 64
#define NTILES (N_DIM / BN)   // 32
#define TILE_BLOCKS (MTILES * NTILES)     // 2048

// Underflow threshold: exp(-t) with t > ~104 rounds to 0 in fp32
#define UNDERFLOW_T 118.0f

// Grid layout
#define XSQ_BLOCKS  (B_DIM / 8)           // 1024
#define MUSQ_BLOCKS (N_DIM / 8)           // 512
#define NORM_BLOCKS (XSQ_BLOCKS + MUSQ_BLOCKS)        // 1536
#define GRID_BLOCKS (NORM_BLOCKS + TILE_BLOCKS)       // 3584

// Scratch (no allocations allowed -> device globals)
__device__ float g_xsq[B_DIM];
__device__ float g_musq[N_DIM];
__device__ unsigned int g_done = 0;    // norm-producer completion counter
__device__ unsigned int g_tdone = 0;   // tile-CTA completion counter (for reset)

// ---------------------------------------------------------------------------
// Single fused kernel.
//   bids [0,1024):      xsq  — one warp per x row
//   bids [1024,1536):   musq — 8 cols x 32 K-slices per CTA
//   bids [1536,3584):   tile CTAs — each owns one 128x128 output tile:
//       1. stream zeros over the tile (valid value if the tile underflows)
//       2. wait for norms (they finish long before the fill stream does)
//       3. guard: bound = (min||x|| - max||mu||)^2; gamma*bound > 118 =>
//          every exp underflows to fp32 zero -> done (zeros already written)
//       4. else exact fp32 GEMM + RBF epilogue overwrites this CTA's zeros
//          (same-CTA program order across __syncthreads -> no write hazard)
// Deadlock-free: norm bids precede tile bids; in-order dispatch guarantees
// all norm CTAs are scheduled before spinning tile CTAs can exhaust slots.
// Counters self-reset by the last tile CTA -> safe under graph replay.
// ---------------------------------------------------------------------------
__global__ __launch_bounds__(256, 6) void fused_rbf_kernel(
    const float* __restrict__ x, const float* __restrict__ mu,
    const float* __restrict__ gamma_p, float* __restrict__ out)
{
    const int tid = threadIdx.x;
    const unsigned bid = blockIdx.x;

    if (bid < NORM_BLOCKS) {
        if (bid < XSQ_BLOCKS) {
            // ---- xsq: warp w handles row bid*8 + w
            const int warp = tid >> 5, lane = tid & 31;
            const int row = bid * 8 + warp;
            const float4* xr = (const float4*)(x + (size_t)row * K_DIM);
            float s = 0.f;
            #pragma unroll
            for (int i = 0; i < 8; i++) {
                float4 v = xr[lane + 32 * i];
                s += v.x * v.x + v.y * v.y + v.z * v.z + v.w * v.w;
            }
            #pragma unroll
            for (int o = 16; o > 0; o >>= 1) s += __shfl_xor_sync(0xffffffffu, s, o);
            if (lane == 0) g_xsq[row] = s;
        } else {
            // ---- musq: CTA covers 8 columns; 32 K-slices of 32 rows each
            const int cb = (bid - XSQ_BLOCKS) * 8;
            const int col = cb + (tid & 7);
            const int ks = tid >> 3;               // 0..31
            const float* p = mu + (size_t)(ks * 32) * N_DIM + col;
            float s = 0.f;
            #pragma unroll 8
            for (int i = 0; i < 32; i++) {
                float v = p[(size_t)i * N_DIM];
                s += v * v;
            }
            __shared__ float sm[32][8];
            sm[ks][tid & 7] = s;
            __syncthreads();
            if (tid < 8) {
                float t = 0.f;
                #pragma unroll
                for (int k = 0; k < 32; k++) t += sm[k][tid];
                g_musq[cb + tid] = t;
            }
        }
        __threadfence();
        __syncthreads();
        if (tid == 0) atomicAdd(&g_done, 1u);
        return;
    }

    // ========================= tile CTA =========================
    const int t = bid - NORM_BLOCKS;                // 0..2047
    const int mt = t >> 5;                          // 0..63  (row tile)
    const int nt = t & 31;                          // 0..31  (col tile)
    const int block_m = mt * BM;
    const int block_n = nt * BN;

    // ---- 1. zero own tile: warp w covers rows w, w+8, ...; lane = col4.
    // Each warp store = one contiguous 512B row segment.
    {
        const int warp = tid >> 5, lane = tid & 31;
        const float4 z = make_float4(0.f, 0.f, 0.f, 0.f);
        #pragma unroll
        for (int r = warp; r < BM; r += 8) {
            float4* row4 = (float4*)(out + (size_t)(block_m + r) * N_DIM + block_n);
            __stcs(&row4[lane], z);
        }
    }

    // ---- 2. wait for norms
    if (tid == 0) {
        volatile unsigned int* p = &g_done;
        while (*p < NORM_BLOCKS) __nanosleep(64);
        __threadfence();
    }
    __syncthreads();

    const float gamma = *gamma_p;

    // ---- 3. guard: min xsq over tile rows, max musq over tile cols
    __shared__ float red[8];
    {
        const int warp = tid >> 5, lane = tid & 31;
        // warps 0-3: min over 128 xsq; warps 4-7: max over 128 musq (negated)
        float v;
        if (tid < 128)      v = g_xsq[block_m + tid];
        else                v = -g_musq[block_n + (tid - 128)];
        #pragma unroll
        for (int o = 16; o > 0; o >>= 1)
            v = fminf(v, __shfl_xor_sync(0xffffffffu, v, o));
        if (lane == 0) red[warp] = v;
        __syncthreads();
    }
    {
        const float mn_x  = fminf(fminf(red[0], red[1]), fminf(red[2], red[3]));
        const float mx_mu = -fminf(fminf(red[4], red[5]), fminf(red[6], red[7]));
        const float d = sqrtf(fmaxf(mn_x, 0.f)) - sqrtf(fmaxf(mx_mu, 0.f));
        if (gamma > 0.f && d > 0.f && gamma * d * d > UNDERFLOW_T) {
            // tile provably all-zero; zeros already streamed
            __syncthreads();
            if (tid == 0) {
                if (atomicAdd(&g_tdone, 1u) == TILE_BLOCKS - 1) {
                    atomicExch(&g_done, 0u);
                    atomicExch(&g_tdone, 0u);
                }
            }
            return;
        }
    }

    // ---- 4. fallback: exact fp32 GEMM + RBF (overwrites own zeros)
    {
        __shared__ float As[BK][BM + APAD];
        __shared__ float Bs[BK][BN];

        const int aRow = tid >> 2;
        const int aCol = (tid & 3) * 4;
        const int bRow = tid >> 5;
        const int bCol = (tid & 31) * 4;
        const int ty = tid >> 4;
        const int tx = tid & 15;

        const float* xg = x + (size_t)(block_m + aRow) * K_DIM + aCol;
        const float* bg = mu + (size_t)bRow * N_DIM + block_n + bCol;

        float acc[TM][TN];
        #pragma unroll
        for (int i = 0; i < TM; i++)
            #pragma unroll
            for (int j = 0; j < TN; j++) acc[i][j] = 0.f;

        __syncthreads();

        for (int k0 = 0; k0 < K_DIM; k0 += BK) {
            float4 a0 = *(const float4*)(xg);
            float4 a1 = *(const float4*)(xg + (size_t)64 * K_DIM);
            As[aCol + 0][aRow] = a0.x;
            As[aCol + 1][aRow] = a0.y;
            As[aCol + 2][aRow] = a0.z;
            As[aCol + 3][aRow] = a0.w;
            As[aCol + 0][aRow + 64] = a1.x;
            As[aCol + 1][aRow + 64] = a1.y;
            As[aCol + 2][aRow + 64] = a1.z;
            As[aCol + 3][aRow + 64] = a1.w;

            float4 b0 = *(const float4*)(bg);
            float4 b1 = *(const float4*)(bg + (size_t)8 * N_DIM);
            *(float4*)&Bs[bRow][bCol]     = b0;
            *(float4*)&Bs[bRow + 8][bCol] = b1;

            __syncthreads();

            #pragma unroll
            for (int k = 0; k < BK; k++) {
                float a_frag[TM], b_frag[TN];
                #pragma unroll
                for (int i = 0; i < TM; i += 4)
                    *(float4*)&a_frag[i] = *(const float4*)&As[k][ty * TM + i];
                #pragma unroll
                for (int j = 0; j < TN; j += 4)
                    *(float4*)&b_frag[j] = *(const float4*)&Bs[k][tx * TN + j];
                #pragma unroll
                for (int i = 0; i < TM; i++)
                    #pragma unroll
                    for (int j = 0; j < TN; j++)
                        acc[i][j] = fmaf(a_frag[i], b_frag[j], acc[i][j]);
            }

            __syncthreads();
            xg += BK;
            bg += (size_t)BK * N_DIM;
        }

        #pragma unroll
        for (int i = 0; i < TM; i++) {
            const int m = block_m + ty * TM + i;
            const float xs = g_xsq[m];
            #pragma unroll
            for (int j = 0; j < TN; j += 4) {
                const int n = block_n + tx * TN + j;
                float4 r;
                r.x = expf(-gamma * (xs + g_musq[n + 0] - 2.f * acc[i][j + 0]));
                r.y = expf(-gamma * (xs + g_musq[n + 1] - 2.f * acc[i][j + 1]));
                r.z = expf(-gamma * (xs + g_musq[n + 2] - 2.f * acc[i][j + 2]));
                r.w = expf(-gamma * (xs + g_musq[n + 3] - 2.f * acc[i][j + 3]));
                *(float4*)&out[(size_t)m * N_DIM + n] = r;
            }
        }
    }

    __syncthreads();
    if (tid == 0) {
        __threadfence();
        if (atomicAdd(&g_tdone, 1u) == TILE_BLOCKS - 1) {
            atomicExch(&g_done, 0u);
            atomicExch(&g_tdone, 0u);
        }
    }
}

// ---------------------------------------------------------------------------
// Launch: inputs per metadata order: x (B*K f32), mu (K*U f32), gamma (1 f32)
// ---------------------------------------------------------------------------
extern "C" void kernel_launch(void* const* d_in, const int* in_sizes, int n_in,
                              void* d_out, int out_size) {
    const float* x     = (const float*)d_in[0];
    const float* mu    = (const float*)d_in[1];
    const float* gamma = (const float*)d_in[2];
    float* out = (float*)d_out;

    fused_rbf_kernel<<<GRID_BLOCKS, 256>>>(x, mu, gamma, out);
}

// round 9
// speedup vs baseline: 1.2105x; 1.2105x over previous
#include <cuda_runtime.h>
#include <math.h>

// Problem dims (fixed by the dataset): x (B, K), mu (K, U), out (B, U)
#define B_DIM 8192
#define K_DIM 1024
#define N_DIM 4096
#define KHALF 512     // guard subset: coordinates [0, KHALF)

// GEMM tiling (fallback path; never taken on this dataset)
#define BM 128
#define BN 128
#define BK 16
#define TM 8
#define TN 8
#define APAD 4

#define MTILES (B_DIM / BM)   // 64
#define NTILES (N_DIM / BN)   // 32
#define NT_PER_CTA 8
#define GUARD_BLOCKS (MTILES * (NTILES / NT_PER_CTA))   // 256

// Underflow threshold: exp(-t) with t > ~104 rounds to 0 in fp32
#define UNDERFLOW_T 118.0f

// Grid layout
#define XSQ_BLOCKS  (B_DIM / 8)           // 1024
#define MUSQ_BLOCKS (N_DIM / 8)           // 512
#define PROD_BLOCKS (XSQ_BLOCKS + MUSQ_BLOCKS)          // 1536
#define FILL_BLOCKS 2048
#define GRID_BLOCKS (PROD_BLOCKS + FILL_BLOCKS + GUARD_BLOCKS)  // 3840

// Scratch (no allocations allowed -> device globals).
// PARTIAL norms over k in [0, KHALF) — lower bounds used ONLY by the guard.
__device__ float g_xsq_p[B_DIM];
__device__ float g_musq_p[N_DIM];
__device__ unsigned int g_done = 0;    // norm-producer completion counter
__device__ unsigned int g_gdone = 0;   // guard-CTA completion counter (reset)

// ---------------------------------------------------------------------------
// Single fused kernel.
//   bids [0,1024):      partial xsq  — one warp per x row, k<512
//   bids [1024,1536):   partial musq — 8 cols x 32 slices of 16 rows, k<512
//   bids [1536,3584):   fill — grid-stride streaming zero stores
//   bids [3584,3840):   guard CTAs (one 128-row tile x 8 col-tiles each):
//       wait for partial norms; per tile bound
//       l2 >= (||x_S|| - ||mu_S||)^2 over the coordinate subset S=[0,512).
//       gamma*bound > 118 -> every exp underflows to fp32 zero (fill already
//       wrote zeros) -> skip. Else: exact fallback — recompute full-precision
//       tile norms in smem + fp32 GEMM + RBF epilogue (correct for ANY input).
// Deadlock-free: producer bids precede guard bids (in-order dispatch).
// Counters self-reset by the last guard CTA -> safe under graph replay.
// ---------------------------------------------------------------------------
__global__ __launch_bounds__(256, 6) void fused_rbf_kernel(
    const float* __restrict__ x, const float* __restrict__ mu,
    const float* __restrict__ gamma_p, float* __restrict__ out)
{
    const int tid = threadIdx.x;
    const unsigned bid = blockIdx.x;

    if (bid < PROD_BLOCKS) {
        if (bid < XSQ_BLOCKS) {
            // ---- partial xsq: warp w handles row bid*8 + w, k in [0,512)
            const int warp = tid >> 5, lane = tid & 31;
            const int row = bid * 8 + warp;
            const float4* xr = (const float4*)(x + (size_t)row * K_DIM);
            float s = 0.f;
            #pragma unroll
            for (int i = 0; i < 4; i++) {          // 128 float4 = 512 floats
                float4 v = xr[lane + 32 * i];
                s += v.x * v.x + v.y * v.y + v.z * v.z + v.w * v.w;
            }
            #pragma unroll
            for (int o = 16; o > 0; o >>= 1) s += __shfl_xor_sync(0xffffffffu, s, o);
            if (lane == 0) g_xsq_p[row] = s;
        } else {
            // ---- partial musq: CTA covers 8 cols; 32 slices of 16 rows (k<512)
            const int cb = (bid - XSQ_BLOCKS) * 8;
            const int col = cb + (tid & 7);
            const int ks = tid >> 3;               // 0..31
            const float* p = mu + (size_t)(ks * 16) * N_DIM + col;
            float s = 0.f;
            #pragma unroll 8
            for (int i = 0; i < 16; i++) {
                float v = p[(size_t)i * N_DIM];
                s += v * v;
            }
            __shared__ float sm[32][8];
            sm[ks][tid & 7] = s;
            __syncthreads();
            if (tid < 8) {
                float t = 0.f;
                #pragma unroll
                for (int k = 0; k < 32; k++) t += sm[k][tid];
                g_musq_p[cb + tid] = t;
            }
        }
        __threadfence();
        __syncthreads();
        if (tid == 0) atomicAdd(&g_done, 1u);
        return;
    }

    if (bid < PROD_BLOCKS + FILL_BLOCKS) {
        // ---- fill: streaming zero stores
        const int fb = bid - PROD_BLOCKS;
        float4* o4 = (float4*)out;
        const float4 z = make_float4(0.f, 0.f, 0.f, 0.f);
        const size_t total = (size_t)B_DIM * N_DIM / 4;   // 8M float4
        const size_t stride = (size_t)FILL_BLOCKS * 256;
        for (size_t i = (size_t)fb * 256 + tid; i < total; i += stride)
            __stcs(&o4[i], z);
        return;
    }

    // ======================= guard + fallback GEMM =======================
    const int g = bid - (PROD_BLOCKS + FILL_BLOCKS);   // 0..255
    const int mt = g >> 2;                             // 0..63
    const int nt0 = (g & 3) * NT_PER_CTA;              // 0,8,16,24
    const int block_m = mt * BM;

    // wait for partial norms (they finish long before the fill stream)
    if (tid == 0) {
        volatile unsigned int* p = &g_done;
        while (*p < PROD_BLOCKS) __nanosleep(64);
        __threadfence();
    }
    __syncthreads();

    const float gamma = *gamma_p;

    // tile reductions: min partial-xsq over 128 rows; per-nt max partial-musq
    __shared__ float red_min[8];
    __shared__ float red_max[8];
    {
        const int warp = tid >> 5, lane = tid & 31;
        float v = (tid < 128) ? g_xsq_p[block_m + tid] : __int_as_float(0x7f800000);
        #pragma unroll
        for (int o = 16; o > 0; o >>= 1)
            v = fminf(v, __shfl_xor_sync(0xffffffffu, v, o));
        if (lane == 0) red_min[warp] = v;

        float mx = 0.f;
        const int base = (nt0 + warp) * BN;
        #pragma unroll
        for (int k = 0; k < 4; k++)
            mx = fmaxf(mx, g_musq_p[base + 32 * k + lane]);
        #pragma unroll
        for (int o = 16; o > 0; o >>= 1)
            mx = fmaxf(mx, __shfl_xor_sync(0xffffffffu, mx, o));
        if (lane == 0) red_max[warp] = mx;
        __syncthreads();
    }
    float rxmin = red_min[0];
    #pragma unroll
    for (int w = 1; w < 8; w++) rxmin = fminf(rxmin, red_min[w]);
    const float rxs = sqrtf(fmaxf(rxmin, 0.f));

    __shared__ float As[BK][BM + APAD];
    __shared__ float Bs[BK][BN];
    __shared__ float xsq_s[BM];
    __shared__ float musq_s[BN];
    __shared__ float part[2][BM];

    for (int j = 0; j < NT_PER_CTA; j++) {
        const float d = rxs - sqrtf(fmaxf(red_max[j], 0.f));
        if (gamma > 0.f && d > 0.f && gamma * d * d > UNDERFLOW_T)
            continue;   // tile provably all-zero; fill already wrote it

        // -------- fallback: exact tile norms + fp32 GEMM + RBF --------
        const int block_n = (nt0 + j) * BN;

        // exact xsq for the tile's 128 rows
        {
            const int r = tid & 127, h = tid >> 7;
            const float4* xr = (const float4*)(x + (size_t)(block_m + r) * K_DIM)
                               + h * (K_DIM / 8);   // 128 float4 per half
            float s = 0.f;
            for (int i = 0; i < K_DIM / 8; i++) {
                float4 v = xr[i];
                s += v.x * v.x + v.y * v.y + v.z * v.z + v.w * v.w;
            }
            __syncthreads();   // smem may be live from a previous tile
            part[h][r] = s;
            __syncthreads();
            if (tid < 128) xsq_s[tid] = part[0][tid] + part[1][tid];
        }
        // exact musq for the tile's 128 cols
        {
            const int c = tid & 127, h = tid >> 7;
            const float* p = mu + (size_t)(h * (K_DIM / 2)) * N_DIM + block_n + c;
            float s = 0.f;
            for (int i = 0; i < K_DIM / 2; i++) {
                float v = p[(size_t)i * N_DIM];
                s += v * v;
            }
            __syncthreads();
            part[h][c] = s;
            __syncthreads();
            if (tid < 128) musq_s[tid] = part[0][tid] + part[1][tid];
            __syncthreads();
        }

        const int aRow = tid >> 2;
        const int aCol = (tid & 3) * 4;
        const int bRow = tid >> 5;
        const int bCol = (tid & 31) * 4;
        const int ty = tid >> 4;
        const int tx = tid & 15;

        const float* xg = x + (size_t)(block_m + aRow) * K_DIM + aCol;
        const float* bg = mu + (size_t)bRow * N_DIM + block_n + bCol;

        float acc[TM][TN];
        #pragma unroll
        for (int i = 0; i < TM; i++)
            #pragma unroll
            for (int jj = 0; jj < TN; jj++) acc[i][jj] = 0.f;

        for (int k0 = 0; k0 < K_DIM; k0 += BK) {
            float4 a0 = *(const float4*)(xg);
            float4 a1 = *(const float4*)(xg + (size_t)64 * K_DIM);
            As[aCol + 0][aRow] = a0.x;
            As[aCol + 1][aRow] = a0.y;
            As[aCol + 2][aRow] = a0.z;
            As[aCol + 3][aRow] = a0.w;
            As[aCol + 0][aRow + 64] = a1.x;
            As[aCol + 1][aRow + 64] = a1.y;
            As[aCol + 2][aRow + 64] = a1.z;
            As[aCol + 3][aRow + 64] = a1.w;

            float4 b0 = *(const float4*)(bg);
            float4 b1 = *(const float4*)(bg + (size_t)8 * N_DIM);
            *(float4*)&Bs[bRow][bCol]     = b0;
            *(float4*)&Bs[bRow + 8][bCol] = b1;

            __syncthreads();

            #pragma unroll
            for (int k = 0; k < BK; k++) {
                float a_frag[TM], b_frag[TN];
                #pragma unroll
                for (int i = 0; i < TM; i += 4)
                    *(float4*)&a_frag[i] = *(const float4*)&As[k][ty * TM + i];
                #pragma unroll
                for (int jj = 0; jj < TN; jj += 4)
                    *(float4*)&b_frag[jj] = *(const float4*)&Bs[k][tx * TN + jj];
                #pragma unroll
                for (int i = 0; i < TM; i++)
                    #pragma unroll
                    for (int jj = 0; jj < TN; jj++)
                        acc[i][jj] = fmaf(a_frag[i], b_frag[jj], acc[i][jj]);
            }

            __syncthreads();
            xg += BK;
            bg += (size_t)BK * N_DIM;
        }

        #pragma unroll
        for (int i = 0; i < TM; i++) {
            const int ml = ty * TM + i;
            const int m = block_m + ml;
            const float xs = xsq_s[ml];
            #pragma unroll
            for (int jj = 0; jj < TN; jj += 4) {
                const int nl = tx * TN + jj;
                const int n = block_n + nl;
                float4 r;
                r.x = expf(-gamma * (xs + musq_s[nl + 0] - 2.f * acc[i][jj + 0]));
                r.y = expf(-gamma * (xs + musq_s[nl + 1] - 2.f * acc[i][jj + 1]));
                r.z = expf(-gamma * (xs + musq_s[nl + 2] - 2.f * acc[i][jj + 2]));
                r.w = expf(-gamma * (xs + musq_s[nl + 3] - 2.f * acc[i][jj + 3]));
                *(float4*)&out[(size_t)m * N_DIM + n] = r;
            }
        }
        __syncthreads();
    }

    // ---- counter self-reset so the next graph replay starts clean
    if (tid == 0) {
        __threadfence();
        if (atomicAdd(&g_gdone, 1u) == GUARD_BLOCKS - 1) {
            atomicExch(&g_done, 0u);
            atomicExch(&g_gdone, 0u);
        }
    }
}

// ---------------------------------------------------------------------------
// Launch: inputs per metadata order: x (B*K f32), mu (K*U f32), gamma (1 f32)
// ---------------------------------------------------------------------------
extern "C" void kernel_launch(void* const* d_in, const int* in_sizes, int n_in,
                              void* d_out, int out_size) {
    const float* x     = (const float*)d_in[0];
    const float* mu    = (const float*)d_in[1];
    const float* gamma = (const float*)d_in[2];
    float* out = (float*)d_out;

    fused_rbf_kernel<<<GRID_BLOCKS, 256>>>(x, mu, gamma, out);
}

// round 10
// speedup vs baseline: 1.2574x; 1.0387x over previous
#include <cuda_runtime.h>
#include <math.h>

// Problem dims (fixed by the dataset): x (B, K), mu (K, U), out (B, U)
#define B_DIM 8192
#define K_DIM 1024
#define N_DIM 4096
#define KHALF 512     // guard subset: coordinates [0, KHALF)

// GEMM tiling (fallback path; never taken on this dataset)
#define BM 128
#define BN 128
#define BK 16
#define TM 8
#define TN 8
#define APAD 4

#define MTILES (B_DIM / BM)   // 64
#define NTILES (N_DIM / BN)   // 32
#define NT_PER_CTA 8
#define GUARD_BLOCKS (MTILES * (NTILES / NT_PER_CTA))   // 256

// Underflow threshold: exp(-t) with t > ~104 rounds to 0 in fp32
#define UNDERFLOW_T 118.0f

// Grid layout: condensed norms first (mixed into wave 1 with fill), guard last
#define XSQ_BLOCKS  128     // 64 rows per CTA (8 warps x 8 rows)
#define MUSQ_BLOCKS 128     // 32 cols per CTA
#define NORM_BLOCKS (XSQ_BLOCKS + MUSQ_BLOCKS)          // 256
#define FILL_BLOCKS 2048
#define GRID_BLOCKS (NORM_BLOCKS + FILL_BLOCKS + GUARD_BLOCKS)  // 2560

// Scratch (no allocations allowed -> device globals).
// PARTIAL norms over k in [0, KHALF) — lower bounds used ONLY by the guard.
__device__ float g_xsq_p[B_DIM];
__device__ float g_musq_p[N_DIM];
__device__ unsigned int g_done = 0;    // norm-producer completion counter
__device__ unsigned int g_gdone = 0;   // guard-CTA completion counter (reset)

// ---------------------------------------------------------------------------
// Single fused kernel.
//   bids [0,128):       partial xsq  — 64 rows/CTA, k<512, high-MLP
//   bids [128,256):     partial musq — 32 cols/CTA, k<512
//   bids [256,2304):    fill — grid-stride streaming zero stores
//   bids [2304,2560):   guard CTAs (one 128-row tile x 8 col-tiles each):
//       wait for partial norms; per tile: l2 >= (||x_S|| - ||mu_S||)^2 over
//       S=[0,512). gamma*bound > 118 -> every exp underflows to fp32 zero
//       (fill already wrote zeros) -> skip. Else exact fallback: recompute
//       full tile norms in smem + fp32 GEMM + RBF (correct for ANY input).
// First dispatch wave contains all 256 norm CTAs (reads) AND ~600 fill CTAs
// (writes), so both HBM directions are busy from t=0.
// Deadlock-free: norm bids precede guard bids (in-order dispatch).
// Counters self-reset by the last guard CTA -> safe under graph replay.
// ---------------------------------------------------------------------------
__global__ __launch_bounds__(256, 6) void fused_rbf_kernel(
    const float* __restrict__ x, const float* __restrict__ mu,
    const float* __restrict__ gamma_p, float* __restrict__ out)
{
    const int tid = threadIdx.x;
    const unsigned bid = blockIdx.x;

    if (bid < NORM_BLOCKS) {
        if (bid < XSQ_BLOCKS) {
            // ---- partial xsq: CTA covers 64 rows; warp w rows w*8..w*8+7
            const int warp = tid >> 5, lane = tid & 31;
            const int row0 = bid * 64 + warp * 8;
            #pragma unroll
            for (int r = 0; r < 8; r++) {
                const float4* xr = (const float4*)(x + (size_t)(row0 + r) * K_DIM);
                float s = 0.f;
                #pragma unroll
                for (int i = 0; i < 4; i++) {      // 128 float4 = 512 floats
                    float4 v = xr[lane + 32 * i];
                    s += v.x * v.x + v.y * v.y + v.z * v.z + v.w * v.w;
                }
                #pragma unroll
                for (int o = 16; o > 0; o >>= 1)
                    s += __shfl_xor_sync(0xffffffffu, s, o);
                if (lane == 0) g_xsq_p[row0 + r] = s;
            }
        } else {
            // ---- partial musq: CTA covers 32 cols; 8 K-slices of 64 rows
            const int cb = (bid - XSQ_BLOCKS) * 32;
            const int col = cb + (tid & 31);
            const int ks = tid >> 5;               // 0..7
            const float* p = mu + (size_t)(ks * 64) * N_DIM + col;
            float s = 0.f;
            #pragma unroll 8
            for (int i = 0; i < 64; i++) {
                float v = p[(size_t)i * N_DIM];
                s += v * v;
            }
            __shared__ float sm[8][32];
            sm[ks][tid & 31] = s;
            __syncthreads();
            if (tid < 32) {
                float t = 0.f;
                #pragma unroll
                for (int k = 0; k < 8; k++) t += sm[k][tid];
                g_musq_p[cb + tid] = t;
            }
        }
        __threadfence();
        __syncthreads();
        if (tid == 0) atomicAdd(&g_done, 1u);
        return;
    }

    if (bid < NORM_BLOCKS + FILL_BLOCKS) {
        // ---- fill: streaming zero stores
        const int fb = bid - NORM_BLOCKS;
        float4* o4 = (float4*)out;
        const float4 z = make_float4(0.f, 0.f, 0.f, 0.f);
        const size_t total = (size_t)B_DIM * N_DIM / 4;   // 8M float4
        const size_t stride = (size_t)FILL_BLOCKS * 256;
        for (size_t i = (size_t)fb * 256 + tid; i < total; i += stride)
            __stcs(&o4[i], z);
        return;
    }

    // ======================= guard + fallback GEMM =======================
    const int g = bid - (NORM_BLOCKS + FILL_BLOCKS);   // 0..255
    const int mt = g >> 2;                             // 0..63
    const int nt0 = (g & 3) * NT_PER_CTA;              // 0,8,16,24
    const int block_m = mt * BM;

    // wait for partial norms (they finish long before the fill stream)
    if (tid == 0) {
        volatile unsigned int* p = &g_done;
        while (*p < NORM_BLOCKS) __nanosleep(64);
        __threadfence();
    }
    __syncthreads();

    const float gamma = *gamma_p;

    // tile reductions: min partial-xsq over 128 rows; per-nt max partial-musq
    __shared__ float red_min[8];
    __shared__ float red_max[8];
    {
        const int warp = tid >> 5, lane = tid & 31;
        float v = (tid < 128) ? g_xsq_p[block_m + tid] : __int_as_float(0x7f800000);
        #pragma unroll
        for (int o = 16; o > 0; o >>= 1)
            v = fminf(v, __shfl_xor_sync(0xffffffffu, v, o));
        if (lane == 0) red_min[warp] = v;

        float mx = 0.f;
        const int base = (nt0 + warp) * BN;
        #pragma unroll
        for (int k = 0; k < 4; k++)
            mx = fmaxf(mx, g_musq_p[base + 32 * k + lane]);
        #pragma unroll
        for (int o = 16; o > 0; o >>= 1)
            mx = fmaxf(mx, __shfl_xor_sync(0xffffffffu, mx, o));
        if (lane == 0) red_max[warp] = mx;
        __syncthreads();
    }
    float rxmin = red_min[0];
    #pragma unroll
    for (int w = 1; w < 8; w++) rxmin = fminf(rxmin, red_min[w]);
    const float rxs = sqrtf(fmaxf(rxmin, 0.f));

    __shared__ float As[BK][BM + APAD];
    __shared__ float Bs[BK][BN];
    __shared__ float xsq_s[BM];
    __shared__ float musq_s[BN];
    __shared__ float part[2][BM];

    for (int j = 0; j < NT_PER_CTA; j++) {
        const float d = rxs - sqrtf(fmaxf(red_max[j], 0.f));
        if (gamma > 0.f && d > 0.f && gamma * d * d > UNDERFLOW_T)
            continue;   // tile provably all-zero; fill already wrote it

        // -------- fallback: exact tile norms + fp32 GEMM + RBF --------
        const int block_n = (nt0 + j) * BN;

        // exact xsq for the tile's 128 rows
        {
            const int r = tid & 127, h = tid >> 7;
            const float4* xr = (const float4*)(x + (size_t)(block_m + r) * K_DIM)
                               + h * (K_DIM / 8);   // 128 float4 per half
            float s = 0.f;
            for (int i = 0; i < K_DIM / 8; i++) {
                float4 v = xr[i];
                s += v.x * v.x + v.y * v.y + v.z * v.z + v.w * v.w;
            }
            __syncthreads();   // smem may be live from a previous tile
            part[h][r] = s;
            __syncthreads();
            if (tid < 128) xsq_s[tid] = part[0][tid] + part[1][tid];
        }
        // exact musq for the tile's 128 cols
        {
            const int c = tid & 127, h = tid >> 7;
            const float* p = mu + (size_t)(h * (K_DIM / 2)) * N_DIM + block_n + c;
            float s = 0.f;
            for (int i = 0; i < K_DIM / 2; i++) {
                float v = p[(size_t)i * N_DIM];
                s += v * v;
            }
            __syncthreads();
            part[h][c] = s;
            __syncthreads();
            if (tid < 128) musq_s[tid] = part[0][tid] + part[1][tid];
            __syncthreads();
        }

        const int aRow = tid >> 2;
        const int aCol = (tid & 3) * 4;
        const int bRow = tid >> 5;
        const int bCol = (tid & 31) * 4;
        const int ty = tid >> 4;
        const int tx = tid & 15;

        const float* xg = x + (size_t)(block_m + aRow) * K_DIM + aCol;
        const float* bg = mu + (size_t)bRow * N_DIM + block_n + bCol;

        float acc[TM][TN];
        #pragma unroll
        for (int i = 0; i < TM; i++)
            #pragma unroll
            for (int jj = 0; jj < TN; jj++) acc[i][jj] = 0.f;

        for (int k0 = 0; k0 < K_DIM; k0 += BK) {
            float4 a0 = *(const float4*)(xg);
            float4 a1 = *(const float4*)(xg + (size_t)64 * K_DIM);
            As[aCol + 0][aRow] = a0.x;
            As[aCol + 1][aRow] = a0.y;
            As[aCol + 2][aRow] = a0.z;
            As[aCol + 3][aRow] = a0.w;
            As[aCol + 0][aRow + 64] = a1.x;
            As[aCol + 1][aRow + 64] = a1.y;
            As[aCol + 2][aRow + 64] = a1.z;
            As[aCol + 3][aRow + 64] = a1.w;

            float4 b0 = *(const float4*)(bg);
            float4 b1 = *(const float4*)(bg + (size_t)8 * N_DIM);
            *(float4*)&Bs[bRow][bCol]     = b0;
            *(float4*)&Bs[bRow + 8][bCol] = b1;

            __syncthreads();

            #pragma unroll
            for (int k = 0; k < BK; k++) {
                float a_frag[TM], b_frag[TN];
                #pragma unroll
                for (int i = 0; i < TM; i += 4)
                    *(float4*)&a_frag[i] = *(const float4*)&As[k][ty * TM + i];
                #pragma unroll
                for (int jj = 0; jj < TN; jj += 4)
                    *(float4*)&b_frag[jj] = *(const float4*)&Bs[k][tx * TN + jj];
                #pragma unroll
                for (int i = 0; i < TM; i++)
                    #pragma unroll
                    for (int jj = 0; jj < TN; jj++)
                        acc[i][jj] = fmaf(a_frag[i], b_frag[jj], acc[i][jj]);
            }

            __syncthreads();
            xg += BK;
            bg += (size_t)BK * N_DIM;
        }

        #pragma unroll
        for (int i = 0; i < TM; i++) {
            const int ml = ty * TM + i;
            const int m = block_m + ml;
            const float xs = xsq_s[ml];
            #pragma unroll
            for (int jj = 0; jj < TN; jj += 4) {
                const int nl = tx * TN + jj;
                const int n = block_n + nl;
                float4 r;
                r.x = expf(-gamma * (xs + musq_s[nl + 0] - 2.f * acc[i][jj + 0]));
                r.y = expf(-gamma * (xs + musq_s[nl + 1] - 2.f * acc[i][jj + 1]));
                r.z = expf(-gamma * (xs + musq_s[nl + 2] - 2.f * acc[i][jj + 2]));
                r.w = expf(-gamma * (xs + musq_s[nl + 3] - 2.f * acc[i][jj + 3]));
                *(float4*)&out[(size_t)m * N_DIM + n] = r;
            }
        }
        __syncthreads();
    }

    // ---- counter self-reset so the next graph replay starts clean
    if (tid == 0) {
        __threadfence();
        if (atomicAdd(&g_gdone, 1u) == GUARD_BLOCKS - 1) {
            atomicExch(&g_done, 0u);
            atomicExch(&g_gdone, 0u);
        }
    }
}

// ---------------------------------------------------------------------------
// Launch: inputs per metadata order: x (B*K f32), mu (K*U f32), gamma (1 f32)
// ---------------------------------------------------------------------------
extern "C" void kernel_launch(void* const* d_in, const int* in_sizes, int n_in,
                              void* d_out, int out_size) {
    const float* x     = (const float*)d_in[0];
    const float* mu    = (const float*)d_in[1];
    const float* gamma = (const float*)d_in[2];
    float* out = (float*)d_out;

    fused_rbf_kernel<<<GRID_BLOCKS, 256>>>(x, mu, gamma, out);
}